// round 13
// baseline (speedup 1.0000x reference)
#include <cuda_runtime.h>
#include <cuda_bf16.h>
#include <math_constants.h>
#include <cstdint>

#define NB 8192
#define GRID_L 576                 // LDG CTAs: 576 x 4 warps x 2 samples = 4608
#define GRID_T 896                 // TMA CTAs: 896 x 4 samples        = 3584
#define GRID_TOTAL (GRID_L + GRID_T)
#define NLDG 4608
#define THREADS 128
#define STG_BYTES 16384
#define MBAR_OFF (2 * STG_BYTES)
#define SLOT_OFF (MBAR_OFF + 64)
#define SMEM_TOTAL (SLOT_OFF + 2 * 4 * 8 * 4)
#define FP_SCALE 32768.0

__device__ unsigned long long g_acc;
__device__ unsigned int g_done;

// Packed fp32x2 ops
#define ADDX2(d, a, b)    asm("add.rn.f32x2 %0,%1,%2;"    : "=l"(d) : "l"(a), "l"(b))
#define FMAX2(d, a, b, c) asm("fma.rn.f32x2 %0,%1,%2,%3;" : "=l"(d) : "l"(a), "l"(b), "l"(c))
#define PACKX2(d, lo, hi) asm("mov.b64 %0,{%1,%2};"       : "=l"(d) : "f"(lo), "f"(hi))
#define UNPACKX2(lo, hi, d) asm("mov.b64 {%0,%1},%2;"     : "=f"(lo), "=f"(hi) : "l"(d))

__device__ __forceinline__ float4 ld4_pf(const float4* p) {
    float4 v;
    asm volatile("ld.global.nc.L2::256B.v4.f32 {%0,%1,%2,%3}, [%4];"
                 : "=f"(v.x), "=f"(v.y), "=f"(v.z), "=f"(v.w) : "l"(p));
    return v;
}
__device__ __forceinline__ uint32_t smem_u32(const void* p) {
    return (uint32_t)__cvta_generic_to_shared(p);
}
__device__ __forceinline__ void mbar_init(uint32_t a, uint32_t cnt) {
    asm volatile("mbarrier.init.shared.b64 [%0], %1;" :: "r"(a), "r"(cnt) : "memory");
}
__device__ __forceinline__ void mbar_expect_tx(uint32_t a, uint32_t bytes) {
    asm volatile("mbarrier.arrive.expect_tx.shared.b64 _, [%0], %1;"
                 :: "r"(a), "r"(bytes) : "memory");
}
__device__ __forceinline__ void bulk_ld(uint32_t dst, const void* src, uint32_t mbar) {
    asm volatile("cp.async.bulk.shared::cta.global.mbarrier::complete_tx::bytes"
                 " [%0], [%1], %2, [%3];"
                 :: "r"(dst), "l"(src), "r"((uint32_t)STG_BYTES), "r"(mbar) : "memory");
}
__device__ __forceinline__ void mbar_wait(uint32_t a, uint32_t parity) {
    asm volatile(
        "{\n\t.reg .pred P;\n"
        "W_%=:\n\t"
        "mbarrier.try_wait.parity.acquire.cta.shared::cta.b64 P, [%0], %1, 0x989680;\n\t"
        "@P bra D_%=;\n\t"
        "bra W_%=;\n"
        "D_%=:\n\t}"
        :: "r"(a), "r"(parity) : "memory");
}

__device__ __forceinline__ void finish_cta(float* out, double loss) {
    const long long q = llrint(loss * FP_SCALE);
    atomicAdd(&g_acc, (unsigned long long)q);
    __threadfence();
    const unsigned int n = atomicAdd(&g_done, 1u);
    if (n == GRID_TOTAL - 1u) {
        const long long totq = (long long)atomicExch(&g_acc, 0ULL);
        g_done = 0;
        out[0] = (float)((double)totq / FP_SCALE);
    }
}

__global__ void __launch_bounds__(THREADS)
loss_kernel(const float* __restrict__ x, float* __restrict__ out) {
    extern __shared__ char smem[];
    const int t = threadIdx.x;
    const int w = t >> 5;
    const int l = t & 31;

    const unsigned long long C23 = 0x4040000040000000ULL; // (2,3)
    const unsigned long long C49 = 0x4110000040800000ULL; // (4,9)

    if (blockIdx.x < GRID_L) {
        // ================= LDG class (R8 shape, samples [0, 4608)) ==========
        __shared__ float wloss[4];
        const int warp_g = blockIdx.x * 4 + w;    // [0, 2304)
        float acc_loss = 0.f;

        #pragma unroll
        for (int s = 0; s < 2; ++s) {
            const int b = warp_g + s * 2304;
            const float4* __restrict__ xp =
                reinterpret_cast<const float4*>(x) + (size_t)b * 1024 + l;

            unsigned long long s0p = 0, Up = 0, Vp = 0, mp1 = 0, mp2 = 0;
            float sy = 0.f;
            float bv = -CUDART_INF_F;
            int   bi = 0x7fffffff;

            float4 buf[4];
            #pragma unroll
            for (int i = 0; i < 4; ++i) buf[i] = ld4_pf(&xp[i * 32]);

            #pragma unroll
            for (int g = 0; g < 8; ++g) {
                float4 nbuf[4];
                if (g < 7) {
                    #pragma unroll
                    for (int i = 0; i < 4; ++i)
                        nbuf[i] = ld4_pf(&xp[(g + 1) * 128 + i * 32]);
                }
                #pragma unroll
                for (int i = 0; i < 4; ++i) {
                    const int c = g * 4 + i;
                    const float X = buf[i].x, Y = buf[i].y, Z = buf[i].z, W = buf[i].w;
                    unsigned long long p0, p1, lsp;
                    PACKX2(p0, X, Y);
                    PACKX2(p1, Z, W);
                    ADDX2(lsp, p0, p1);
                    ADDX2(s0p, s0p, lsp);
                    ADDX2(Up,  Up,  s0p);
                    ADDX2(Vp,  Vp,  Up);
                    FMAX2(mp1, p1, C23, mp1);
                    FMAX2(mp2, p1, C49, mp2);
                    sy += Y;
                    const float m = fmaxf(fmaxf(X, Y), fmaxf(Z, W));
                    if (m > bv) {
                        bv = m;
                        const int cc = (m == X) ? 0 : ((m == Y) ? 1 : ((m == Z) ? 2 : 3));
                        bi = ((c * 32 + l) << 2) + cc;
                    }
                }
                #pragma unroll
                for (int i = 0; i < 4; ++i) buf[i] = nbuf[i];
            }

            float s0lo, s0hi, Ulo, Uhi, Vlo, Vhi, m1lo, m1hi, m2lo, m2hi;
            UNPACKX2(s0lo, s0hi, s0p);
            UNPACKX2(Ulo, Uhi, Up);
            UNPACKX2(Vlo, Vhi, Vp);
            UNPACKX2(m1lo, m1hi, mp1);
            UNPACKX2(m2lo, m2hi, mp2);

            float s0 = s0lo + s0hi;
            const float cU = Ulo + Uhi;
            const float cV = Vlo + Vhi;
            const float sc1 = fmaf(32.f, s0, -cU);
            const float sc2 = fmaf(1024.f, s0, fmaf(-65.f, cU, 2.f * cV));
            const float jh = (float)(l >> 4);
            float sj  = fmaf(2.f, sc1, jh * s0);
            float sjj = fmaf(4.f, sc2, fmaf(4.f * jh, sc1, jh * s0));
            const float m1 = sy + m1lo + m1hi;
            const float m2 = sy + m2lo + m2hi;
            const float k0 = (float)((l & 15) << 2);
            float sk  = fmaf(k0, s0, m1);
            const float skk = fmaf(k0 * k0, s0, fmaf(2.f * k0, m1, m2));
            float sq = sjj + skk;

            #pragma unroll
            for (int off = 16; off > 0; off >>= 1) {
                s0 += __shfl_down_sync(0xffffffffu, s0, off);
                sj += __shfl_down_sync(0xffffffffu, sj, off);
                sk += __shfl_down_sync(0xffffffffu, sk, off);
                sq += __shfl_down_sync(0xffffffffu, sq, off);
                const float ov = __shfl_down_sync(0xffffffffu, bv, off);
                const int   oi = __shfl_down_sync(0xffffffffu, bi, off);
                if (ov > bv || (ov == bv && oi < bi)) { bv = ov; bi = oi; }
            }
            if (l == 0) {
                const float mx = (float)(bi >> 6);
                const float my = (float)(bi & 63);
                acc_loss += (mx * mx + my * my) * s0
                          - 2.f * mx * sj - 2.f * my * sk + sq;
            }
        }

        if (l == 0) wloss[w] = acc_loss;
        __syncthreads();
        if (t == 0) {
            finish_cta(out, (double)wloss[0] + (double)wloss[1]
                          + (double)wloss[2] + (double)wloss[3]);
        }
    } else {
        // ============ Bulk-TMA class (R7 shape, samples [4608, 8192)) =======
        float* slots = reinterpret_cast<float*>(smem + SLOT_OFF);
        const int b0 = NLDG + (blockIdx.x - GRID_L) * 4;
        const uint32_t mb = smem_u32(smem + MBAR_OFF);
        const uint32_t st = smem_u32(smem);

        if (t == 0) {
            mbar_init(mb + 0, 1u);
            mbar_init(mb + 8, 1u);
        }
        __syncthreads();
        if (t == 0) {
            mbar_expect_tx(mb + 0, STG_BYTES);
            bulk_ld(st + 0,          x + (size_t)(b0 + 0) * 4096, mb + 0);
            mbar_expect_tx(mb + 8, STG_BYTES);
            bulk_ld(st + STG_BYTES,  x + (size_t)(b0 + 1) * 4096, mb + 8);
        }

        double loss_acc = 0.0;

        #pragma unroll
        for (int smp = 0; smp < 4; ++smp) {
            const int stage  = smp & 1;
            const int parity = smp >> 1;
            mbar_wait(mb + stage * 8, (uint32_t)parity);

            const float4* sp =
                reinterpret_cast<const float4*>(smem + stage * STG_BYTES) + t;
            float4 v[8];
            #pragma unroll
            for (int it = 0; it < 8; ++it) v[it] = sp[it * 128];

            unsigned long long s0p = 0, Up = 0, Vp = 0, mp1 = 0, mp2 = 0;
            float sy = 0.f;
            float bv = -CUDART_INF_F;
            int   bi = 0x7fffffff;

            #pragma unroll
            for (int it = 0; it < 8; ++it) {
                const float X = v[it].x, Y = v[it].y, Z = v[it].z, W = v[it].w;
                unsigned long long p0, p1, lsp;
                PACKX2(p0, X, Y);
                PACKX2(p1, Z, W);
                ADDX2(lsp, p0, p1);
                ADDX2(s0p, s0p, lsp);
                ADDX2(Up,  Up,  s0p);
                ADDX2(Vp,  Vp,  Up);
                FMAX2(mp1, p1, C23, mp1);
                FMAX2(mp2, p1, C49, mp2);
                sy += Y;
                const float m = fmaxf(fmaxf(X, Y), fmaxf(Z, W));
                if (m > bv) {
                    bv = m;
                    const int cc = (m == X) ? 0 : ((m == Y) ? 1 : ((m == Z) ? 2 : 3));
                    bi = ((it * 128 + t) << 2) + cc;
                }
            }

            float s0lo, s0hi, Ulo, Uhi, Vlo, Vhi, m1lo, m1hi, m2lo, m2hi;
            UNPACKX2(s0lo, s0hi, s0p);
            UNPACKX2(Ulo, Uhi, Up);
            UNPACKX2(Vlo, Vhi, Vp);
            UNPACKX2(m1lo, m1hi, mp1);
            UNPACKX2(m2lo, m2hi, mp2);

            float s0 = s0lo + s0hi;
            const float cU = Ulo + Uhi;
            const float cV = Vlo + Vhi;
            const float si1 = fmaf(8.f, s0, -cU);
            const float si2 = fmaf(64.f, s0, fmaf(-17.f, cU, 2.f * cV));
            const float jb = (float)(t >> 4);
            float sj  = fmaf(8.f, si1, jb * s0);
            float sjj = fmaf(64.f, si2, fmaf(16.f * jb, si1, jb * jb * s0));
            const float m1 = sy + m1lo + m1hi;
            const float m2 = sy + m2lo + m2hi;
            const float k0 = (float)((t & 15) << 2);
            float sk  = fmaf(k0, s0, m1);
            const float skk = fmaf(k0 * k0, s0, fmaf(2.f * k0, m1, m2));
            float sq = sjj + skk;

            #pragma unroll
            for (int off = 16; off > 0; off >>= 1) {
                s0 += __shfl_down_sync(0xffffffffu, s0, off);
                sj += __shfl_down_sync(0xffffffffu, sj, off);
                sk += __shfl_down_sync(0xffffffffu, sk, off);
                sq += __shfl_down_sync(0xffffffffu, sq, off);
                const float ov = __shfl_down_sync(0xffffffffu, bv, off);
                const int   oi = __shfl_down_sync(0xffffffffu, bi, off);
                if (ov > bv || (ov == bv && oi < bi)) { bv = ov; bi = oi; }
            }

            float* slot = slots + (smp & 1) * 32 + w * 8;
            if (l == 0) {
                slot[0] = s0; slot[1] = sj; slot[2] = sk; slot[3] = sq;
                slot[4] = bv; reinterpret_cast<int*>(slot)[5] = bi;
            }
            __syncthreads();   // slots ready AND stage fully consumed

            if (t == 0) {
                if (smp < 2) {  // refill drained stage with sample smp+2
                    mbar_expect_tx(mb + stage * 8, STG_BYTES);
                    bulk_ld(st + stage * STG_BYTES,
                            x + (size_t)(b0 + smp + 2) * 4096, mb + stage * 8);
                }
                const float* sl = slots + (smp & 1) * 32;
                float fs0 = sl[0], fsj = sl[1], fsk = sl[2], fsq = sl[3];
                float fbv = sl[4]; int fbi = reinterpret_cast<const int*>(sl)[5];
                #pragma unroll
                for (int ww = 1; ww < 4; ++ww) {
                    const float* s2 = sl + ww * 8;
                    fs0 += s2[0]; fsj += s2[1]; fsk += s2[2]; fsq += s2[3];
                    const float ov = s2[4];
                    const int   oi = reinterpret_cast<const int*>(s2)[5];
                    if (ov > fbv || (ov == fbv && oi < fbi)) { fbv = ov; fbi = oi; }
                }
                const float mx = (float)(fbi >> 6);
                const float my = (float)(fbi & 63);
                loss_acc += (double)((mx * mx + my * my) * fs0
                                     - 2.f * mx * fsj - 2.f * my * fsk + fsq);
            }
        }

        if (t == 0) finish_cta(out, loss_acc);
    }
}

extern "C" void kernel_launch(void* const* d_in, const int* in_sizes, int n_in,
                              void* d_out, int out_size) {
    const float* x = (const float*)d_in[0];
    float* out = (float*)d_out;
    loss_kernel<<<GRID_TOTAL, THREADS, SMEM_TOTAL>>>(x, out);
}

// round 14
// speedup vs baseline: 1.0655x; 1.0655x over previous
#include <cuda_runtime.h>
#include <cuda_bf16.h>
#include <math_constants.h>

#define NB 8192
#define GRID 1024           // 1024 CTAs x 4 warps x 2 samples = 8192 samples
#define THREADS 128
#define FP_SCALE 32768.0    // 2^15 fixed point (deterministic integer accumulation)

__device__ unsigned long long g_acc;
__device__ unsigned int g_done;

// Packed fp32x2 ops (Blackwell FFMA2 path — PTX-only)
#define ADDX2(d, a, b)    asm("add.rn.f32x2 %0,%1,%2;"    : "=l"(d) : "l"(a), "l"(b))
#define FMAX2(d, a, b, c) asm("fma.rn.f32x2 %0,%1,%2,%3;" : "=l"(d) : "l"(a), "l"(b), "l"(c))
#define PACKX2(d, lo, hi) asm("mov.b64 %0,{%1,%2};"       : "=l"(d) : "f"(lo), "f"(hi))
#define UNPACKX2(lo, hi, d) asm("mov.b64 {%0,%1},%2;"     : "=f"(lo), "=f"(hi) : "l"(d))

// 128-bit load, 256B L2 refill granularity — the one proven bandwidth lever
// (5.2 -> 5.56 TB/s on this rolling-prefetch shape).
__device__ __forceinline__ float4 ld4_pf(const float4* p) {
    float4 v;
    asm volatile("ld.global.nc.L2::256B.v4.f32 {%0,%1,%2,%3}, [%4];"
                 : "=f"(v.x), "=f"(v.y), "=f"(v.z), "=f"(v.w) : "l"(p));
    return v;
}

// Release-scoped accumulate: orders the value-add before the counter-add
// without a full CTA MEMBAR.
__device__ __forceinline__ void acc_release(unsigned long long* p, unsigned long long v) {
    asm volatile("red.release.gpu.global.add.u64 [%0], %1;" :: "l"(p), "l"(v) : "memory");
}
__device__ __forceinline__ unsigned int inc_acqrel(unsigned int* p) {
    unsigned int old;
    asm volatile("atom.acq_rel.gpu.global.add.u32 %0, [%1], 1;" : "=r"(old) : "l"(p) : "memory");
    return old;
}

__global__ void __launch_bounds__(THREADS, 7)
loss_kernel(const float* __restrict__ x, float* __restrict__ out) {
    const int t = threadIdx.x;
    const int w = t >> 5;
    const int l = t & 31;
    const int warp_g = blockIdx.x * 4 + w;

    __shared__ float wloss[4];

    const unsigned long long C23 = 0x4040000040000000ULL; // (2.0f, 3.0f)
    const unsigned long long C49 = 0x4110000040800000ULL; // (4.0f, 9.0f)

    float acc_loss = 0.f;

    #pragma unroll
    for (int s = 0; s < 2; ++s) {
        const int b = warp_g + s * 4096;
        const float4* __restrict__ xp =
            reinterpret_cast<const float4*>(x) + (size_t)b * 1024 + l;

        // Packed accumulators (bit-zero == (0.f, 0.f))
        unsigned long long s0p = 0, Up = 0, Vp = 0, mp1 = 0, mp2 = 0;
        float sy = 0.f;
        float bv = -CUDART_INF_F;
        int   bi = 0x7fffffff;

        // 4-deep rolling prefetch over 32 chunks (8 groups of 4)
        float4 buf[4];
        #pragma unroll
        for (int i = 0; i < 4; ++i) buf[i] = ld4_pf(&xp[i * 32]);

        #pragma unroll
        for (int g = 0; g < 8; ++g) {
            float4 nbuf[4];
            if (g < 7) {
                #pragma unroll
                for (int i = 0; i < 4; ++i)
                    nbuf[i] = ld4_pf(&xp[(g + 1) * 128 + i * 32]);
            }
            #pragma unroll
            for (int i = 0; i < 4; ++i) {
                const int c = g * 4 + i;            // chunk index 0..31
                const float X = buf[i].x, Y = buf[i].y, Z = buf[i].z, W = buf[i].w;
                unsigned long long p0, p1, lsp;
                PACKX2(p0, X, Y);
                PACKX2(p1, Z, W);
                ADDX2(lsp, p0, p1);                 // (X+Z, Y+W)
                ADDX2(s0p, s0p, lsp);               // running sum
                ADDX2(Up,  Up,  s0p);               // prefix of prefix -> c-moment
                ADDX2(Vp,  Vp,  Up);                // -> c^2-moment
                FMAX2(mp1, p1, C23, mp1);           // 2Z + 3W
                FMAX2(mp2, p1, C49, mp2);           // 4Z + 9W
                sy += Y;                            // Y coeff is 1 in both m1,m2

                const float m = fmaxf(fmaxf(X, Y), fmaxf(Z, W));
                if (m > bv) {                       // first-max: strict '>', c ascending
                    bv = m;
                    const int cc = (m == X) ? 0 : ((m == Y) ? 1 : ((m == Z) ? 2 : 3));
                    bi = ((c * 32 + l) << 2) + cc;
                }
            }
            #pragma unroll
            for (int i = 0; i < 4; ++i) buf[i] = nbuf[i];
        }

        // ---- fold packed accumulators ----
        float s0lo, s0hi, Ulo, Uhi, Vlo, Vhi, m1lo, m1hi, m2lo, m2hi;
        UNPACKX2(s0lo, s0hi, s0p);
        UNPACKX2(Ulo, Uhi, Up);
        UNPACKX2(Vlo, Vhi, Vp);
        UNPACKX2(m1lo, m1hi, mp1);
        UNPACKX2(m2lo, m2hi, mp2);

        float s0 = s0lo + s0hi;
        const float cU = Ulo + Uhi;
        const float cV = Vlo + Vhi;
        // Sum c*ls = 32*s0 - U ;  Sum c^2*ls = 1024*s0 - 65*U + 2*V
        const float sc1 = fmaf(32.f, s0, -cU);
        const float sc2 = fmaf(1024.f, s0, fmaf(-65.f, cU, 2.f * cV));
        // j = 2c + jh
        const float jh = (float)(l >> 4);
        float sj  = fmaf(2.f, sc1, jh * s0);
        float sjj = fmaf(4.f, sc2, fmaf(4.f * jh, sc1, jh * s0)); // jh^2 == jh
        // k = k0 + cc  (k0 thread-constant)
        const float m1 = sy + m1lo + m1hi;
        const float m2 = sy + m2lo + m2hi;
        const float k0 = (float)((l & 15) << 2);
        float sk  = fmaf(k0, s0, m1);
        const float skk = fmaf(k0 * k0, s0, fmaf(2.f * k0, m1, m2));
        float sq = sjj + skk;

        // ---- warp-only reduction ----
        #pragma unroll
        for (int off = 16; off > 0; off >>= 1) {
            s0 += __shfl_down_sync(0xffffffffu, s0, off);
            sj += __shfl_down_sync(0xffffffffu, sj, off);
            sk += __shfl_down_sync(0xffffffffu, sk, off);
            sq += __shfl_down_sync(0xffffffffu, sq, off);
            const float ov = __shfl_down_sync(0xffffffffu, bv, off);
            const int   oi = __shfl_down_sync(0xffffffffu, bi, off);
            if (ov > bv || (ov == bv && oi < bi)) { bv = ov; bi = oi; }
        }

        if (l == 0) {
            const float mx = (float)(bi >> 6);
            const float my = (float)(bi & 63);
            acc_loss += (mx * mx + my * my) * s0
                      - 2.f * mx * sj
                      - 2.f * my * sk
                      + sq;
        }
    }

    if (l == 0) wloss[w] = acc_loss;
    __syncthreads();

    if (t == 0) {
        const double tot = (double)wloss[0] + (double)wloss[1]
                         + (double)wloss[2] + (double)wloss[3];
        const long long q = llrint(tot * FP_SCALE);
        // release-add then acq_rel counter: same ordering guarantee as the
        // old __threadfence pair, one MEMBAR cheaper.
        acc_release(&g_acc, (unsigned long long)q);
        const unsigned int n = inc_acqrel(&g_done);
        if (n == GRID - 1u) {
            const long long totq = (long long)atomicExch(&g_acc, 0ULL);
            g_done = 0;
            out[0] = (float)((double)totq / FP_SCALE);
        }
    }
}

extern "C" void kernel_launch(void* const* d_in, const int* in_sizes, int n_in,
                              void* d_out, int out_size) {
    const float* x = (const float*)d_in[0];
    float* out = (float*)d_out;
    loss_kernel<<<GRID, THREADS>>>(x, out);
}

// round 15
// speedup vs baseline: 1.0743x; 1.0083x over previous
#include <cuda_runtime.h>
#include <cuda_bf16.h>
#include <math_constants.h>

#define NB 8192
#define GRID 1024           // 1024 CTAs x 4 warps x 2 samples = 8192 samples
#define THREADS 128
#define FP_SCALE 32768.0    // 2^15 fixed point (deterministic integer accumulation)

__device__ unsigned long long g_acc;
__device__ unsigned int g_done;

// Packed fp32x2 ops (Blackwell FFMA2 path — PTX-only)
#define ADDX2(d, a, b)    asm("add.rn.f32x2 %0,%1,%2;"    : "=l"(d) : "l"(a), "l"(b))
#define FMAX2(d, a, b, c) asm("fma.rn.f32x2 %0,%1,%2,%3;" : "=l"(d) : "l"(a), "l"(b), "l"(c))
#define PACKX2(d, lo, hi) asm("mov.b64 %0,{%1,%2};"       : "=l"(d) : "f"(lo), "f"(hi))
#define UNPACKX2(lo, hi, d) asm("mov.b64 {%0,%1},%2;"     : "=f"(lo), "=f"(hi) : "l"(d))

// 128-bit load with 256B L2 refill granularity: the one measured bandwidth
// lever for this read-once stream (5.2 -> 5.56 TB/s on this shape).
__device__ __forceinline__ float4 ld4_pf(const float4* p) {
    float4 v;
    asm volatile("ld.global.nc.L2::256B.v4.f32 {%0,%1,%2,%3}, [%4];"
                 : "=f"(v.x), "=f"(v.y), "=f"(v.z), "=f"(v.w) : "l"(p));
    return v;
}

__global__ void __launch_bounds__(THREADS, 7)
loss_kernel(const float* __restrict__ x, float* __restrict__ out) {
    const int t = threadIdx.x;
    const int w = t >> 5;
    const int l = t & 31;
    const int warp_g = blockIdx.x * 4 + w;

    __shared__ float wloss[4];

    const unsigned long long C23 = 0x4040000040000000ULL; // (2.0f, 3.0f)
    const unsigned long long C49 = 0x4110000040800000ULL; // (4.0f, 9.0f)

    float acc_loss = 0.f;

    #pragma unroll
    for (int s = 0; s < 2; ++s) {
        const int b = warp_g + s * 4096;
        const float4* __restrict__ xp =
            reinterpret_cast<const float4*>(x) + (size_t)b * 1024 + l;

        // Packed accumulators (bit-zero == (0.f, 0.f))
        unsigned long long s0p = 0, Up = 0, Vp = 0, mp1 = 0, mp2 = 0;
        float sy = 0.f;
        float bv = -CUDART_INF_F;
        int   bi = 0x7fffffff;

        // 4-deep rolling prefetch over 32 chunks (8 groups of 4)
        float4 buf[4];
        #pragma unroll
        for (int i = 0; i < 4; ++i) buf[i] = ld4_pf(&xp[i * 32]);

        #pragma unroll
        for (int g = 0; g < 8; ++g) {
            float4 nbuf[4];
            if (g < 7) {
                #pragma unroll
                for (int i = 0; i < 4; ++i)
                    nbuf[i] = ld4_pf(&xp[(g + 1) * 128 + i * 32]);
            }
            #pragma unroll
            for (int i = 0; i < 4; ++i) {
                const int c = g * 4 + i;            // chunk index 0..31
                const float X = buf[i].x, Y = buf[i].y, Z = buf[i].z, W = buf[i].w;
                unsigned long long p0, p1, lsp;
                PACKX2(p0, X, Y);
                PACKX2(p1, Z, W);
                ADDX2(lsp, p0, p1);                 // (X+Z, Y+W)
                ADDX2(s0p, s0p, lsp);               // running sum
                ADDX2(Up,  Up,  s0p);               // prefix of prefix -> c-moment
                ADDX2(Vp,  Vp,  Up);                // -> c^2-moment
                FMAX2(mp1, p1, C23, mp1);           // 2Z + 3W
                FMAX2(mp2, p1, C49, mp2);           // 4Z + 9W
                sy += Y;                            // Y coeff is 1 in both m1,m2

                const float m = fmaxf(fmaxf(X, Y), fmaxf(Z, W));
                if (m > bv) {                       // first-max: strict '>', c ascending
                    bv = m;
                    const int cc = (m == X) ? 0 : ((m == Y) ? 1 : ((m == Z) ? 2 : 3));
                    bi = ((c * 32 + l) << 2) + cc;
                }
            }
            #pragma unroll
            for (int i = 0; i < 4; ++i) buf[i] = nbuf[i];
        }

        // ---- fold packed accumulators ----
        float s0lo, s0hi, Ulo, Uhi, Vlo, Vhi, m1lo, m1hi, m2lo, m2hi;
        UNPACKX2(s0lo, s0hi, s0p);
        UNPACKX2(Ulo, Uhi, Up);
        UNPACKX2(Vlo, Vhi, Vp);
        UNPACKX2(m1lo, m1hi, mp1);
        UNPACKX2(m2lo, m2hi, mp2);

        float s0 = s0lo + s0hi;
        const float cU = Ulo + Uhi;
        const float cV = Vlo + Vhi;
        // Sum c*ls = 32*s0 - U ;  Sum c^2*ls = 1024*s0 - 65*U + 2*V
        const float sc1 = fmaf(32.f, s0, -cU);
        const float sc2 = fmaf(1024.f, s0, fmaf(-65.f, cU, 2.f * cV));
        // j = 2c + jh
        const float jh = (float)(l >> 4);
        float sj  = fmaf(2.f, sc1, jh * s0);
        float sjj = fmaf(4.f, sc2, fmaf(4.f * jh, sc1, jh * s0)); // jh^2 == jh
        // k = k0 + cc  (k0 thread-constant)
        const float m1 = sy + m1lo + m1hi;
        const float m2 = sy + m2lo + m2hi;
        const float k0 = (float)((l & 15) << 2);
        float sk  = fmaf(k0, s0, m1);
        const float skk = fmaf(k0 * k0, s0, fmaf(2.f * k0, m1, m2));
        float sq = sjj + skk;

        // ---- warp-only reduction ----
        #pragma unroll
        for (int off = 16; off > 0; off >>= 1) {
            s0 += __shfl_down_sync(0xffffffffu, s0, off);
            sj += __shfl_down_sync(0xffffffffu, sj, off);
            sk += __shfl_down_sync(0xffffffffu, sk, off);
            sq += __shfl_down_sync(0xffffffffu, sq, off);
            const float ov = __shfl_down_sync(0xffffffffu, bv, off);
            const int   oi = __shfl_down_sync(0xffffffffu, bi, off);
            if (ov > bv || (ov == bv && oi < bi)) { bv = ov; bi = oi; }
        }

        if (l == 0) {
            const float mx = (float)(bi >> 6);
            const float my = (float)(bi & 63);
            acc_loss += (mx * mx + my * my) * s0
                      - 2.f * mx * sj
                      - 2.f * my * sk
                      + sq;
        }
    }

    if (l == 0) wloss[w] = acc_loss;
    __syncthreads();

    if (t == 0) {
        const double tot = (double)wloss[0] + (double)wloss[1]
                         + (double)wloss[2] + (double)wloss[3];
        const long long q = llrint(tot * FP_SCALE);
        atomicAdd(&g_acc, (unsigned long long)q);
        __threadfence();
        const unsigned int n = atomicAdd(&g_done, 1u);
        if (n == GRID - 1u) {
            const long long totq = (long long)atomicExch(&g_acc, 0ULL);
            g_done = 0;
            out[0] = (float)((double)totq / FP_SCALE);
        }
    }
}

extern "C" void kernel_launch(void* const* d_in, const int* in_sizes, int n_in,
                              void* d_out, int out_size) {
    const float* x = (const float*)d_in[0];
    float* out = (float*)d_out;
    loss_kernel<<<GRID, THREADS>>>(x, out);
}